// round 7
// baseline (speedup 1.0000x reference)
#include <cuda_runtime.h>
#include <math.h>

// Problem constants (fixed by the reference)
#define BB 256
#define TT 200
#define QQ 1000
#define TM1 199    // T - 1
#define NTHR 128   // 4 warps; two 64-thread halves, one student each
#define HALF 64
#define KPT 4      // steps per thread (stride HALF)
#define NCTA (BB / 2)   // 128 CTAs -> at most one per SM

// Fixed-point: per-student loss (< 8.0) scaled by 2^40; 256 of them < 2^51.
// Completion count lives at bit 54: one atomicAdd carries payload + ticket(s).
#define FXSCALE 1099511627776.0          // 2^40
#define CNT_ONE (1ull << 54)
#define SUM_MASK ((1ull << 54) - 1ull)

__device__ unsigned long long g_acc = 0ull;   // packed {count[63:54], fxsum[53:0]}

__global__ void __launch_bounds__(NTHR)
fused_kernel(const float* __restrict__ logit_c,
             const float* __restrict__ logit_t,
             const int*   __restrict__ q_idx,
             const int*   __restrict__ correct,
             float*       __restrict__ out)
{
    __shared__ float sh_wsum[4];
    __shared__ int   sh_wval[4];
    __shared__ float sh_e[2][TM1 + 1];    // fallback only
    __shared__ float sh_pc[2][TM1 + 1];   // fallback only

    const int i    = threadIdx.x;
    const int lane = i & 31;
    const int warp = i >> 5;
    const int half = warp >> 1;               // 0 or 1 -> which student
    const int j    = i & (HALF - 1);          // thread index within half
    const int s    = blockIdx.x * 2 + half;   // student id

    float* __restrict__ p_mean = out + 1;
    float* __restrict__ gt     = out + 1 + (size_t)BB * TM1;

    // ---- Pass 1: batched index/label loads (coalesced within each half) ----
    int   qv[KPT];
    float av[KPT];
    bool  actv[KPT];
    #pragma unroll
    for (int k = 0; k < KPT; k++) {
        const int idx = j + k * HALF;
        actv[k] = (idx < TM1);
        const int base = s * TT + idx + 1;
        qv[k] = actv[k] ? q_idx[base]          : 0;
        av[k] = actv[k] ? (float)correct[base] : 0.0f;
    }

    // ---- Pass 2: batched logit gathers (8 independent LDGs in flight) ----
    float xcv[KPT], xtv[KPT];
    #pragma unroll
    for (int k = 0; k < KPT; k++) {
        if (actv[k]) {
            const int idx = j + k * HALF;
            const size_t row = (size_t)(s * TT + idx) * QQ + qv[k];
            xcv[k] = logit_c[row];
            xtv[k] = logit_t[row];
        } else { xcv[k] = 0.0f; xtv[k] = 0.0f; }
    }

    // ---- Pass 3: compute + elementwise outputs ----
    float ev[KPT], pcv[KPT];
    float e_acc = 0.0f;
    bool  allpos = true;
    #pragma unroll
    for (int k = 0; k < KPT; k++) {
        if (actv[k]) {
            const float ec = __expf(-xcv[k]);
            const float et = __expf(-xtv[k]);
            const float pc = __fdividef(1.0f, 1.0f + ec);
            const float pt = __fdividef(1.0f, 1.0f + et);
            const int idx = j + k * HALF;
            const size_t o = (size_t)s * TM1 + idx;
            p_mean[o] = 0.5f * (pt + pc);
            gt[o]     = av[k];
            // BCE(sigmoid(x),a) = (1-a)*x + log1p(e^{-x}); both terms in one log
            const float e = (1.0f - av[k]) * (xcv[k] + xtv[k])
                          + __logf((1.0f + ec) * (1.0f + et));
            ev[k] = e; pcv[k] = pc;
            e_acc += e;
            allpos = allpos && (pc > 0.0f);
        } else { ev[k] = 0.0f; pcv[k] = 1.0f; }
    }

    // ---- Reduce: per-warp sum + validity, ONE barrier on fast path ----
    float v = e_acc;
    #pragma unroll
    for (int off = 16; off > 0; off >>= 1)
        v += __shfl_xor_sync(0xFFFFFFFFu, v, off);
    const int wall = __all_sync(0xFFFFFFFFu, allpos);
    if (lane == 0) { sh_wsum[warp] = v; sh_wval[warp] = wall; }
    __syncthreads();

    const int validA = sh_wval[0] & sh_wval[1];
    const int validB = sh_wval[2] & sh_wval[3];

    if (validA & validB) {
        // Fast path: both students full-mask, count = 199 each.
        // One atomic carries BOTH losses + two tickets.
        if (i == 0) {
            const double lossA = (double)(sh_wsum[0] + sh_wsum[1]) * (1.0 / (double)TM1);
            const double lossB = (double)(sh_wsum[2] + sh_wsum[3]) * (1.0 / (double)TM1);
            const unsigned long long fx =
                __double2ull_rn(lossA * FXSCALE) +
                __double2ull_rn(lossB * FXSCALE) + 2ull * CNT_ONE;
            const unsigned long long now = atomicAdd(&g_acc, fx) + fx;
            if ((now >> 54) == (unsigned long long)BB) {
                out[0] = (float)((double)(now & SUM_MASK) * (1.0 / FXSCALE));
                g_acc  = 0ull;              // reset for next graph replay
            }
        }
    } else {
        // Rare exact dynamic-trim fallback (per failing student)
        #pragma unroll
        for (int k = 0; k < KPT; k++) {
            const int idx = j + k * HALF;
            if (actv[k]) { sh_e[half][idx] = ev[k]; sh_pc[half][idx] = pcv[k]; }
        }
        __syncthreads();
        if (i == 0) {
            double lsum = 0.0;
            #pragma unroll
            for (int h = 0; h < 2; h++) {
                const int hv = (h == 0) ? validA : validB;
                if (hv) {
                    const float esum = sh_wsum[2 * h] + sh_wsum[2 * h + 1];
                    lsum += (double)esum * (1.0 / (double)TM1);
                } else {
                    int last = -1;
                    for (int jj = 0; jj < TM1; jj++)
                        if (sh_pc[h][jj] > 0.0f) last = jj;
                    if (last < 0) last = TM1 - 1;   // argmax-of-all-false convention
                    float sum = 0.0f;
                    for (int jj = 0; jj <= last; jj++) sum += sh_e[h][jj];
                    lsum += (double)sum / (double)(last + 1);
                }
            }
            const unsigned long long fx =
                __double2ull_rn(lsum * FXSCALE) + 2ull * CNT_ONE;
            const unsigned long long now = atomicAdd(&g_acc, fx) + fx;
            if ((now >> 54) == (unsigned long long)BB) {
                out[0] = (float)((double)(now & SUM_MASK) * (1.0 / FXSCALE));
                g_acc  = 0ull;
            }
        }
    }
}

extern "C" void kernel_launch(void* const* d_in, const int* in_sizes, int n_in,
                              void* d_out, int out_size)
{
    const float* logit_c = (const float*)d_in[0];
    const float* logit_t = (const float*)d_in[1];
    const int*   q_idx   = (const int*)d_in[2];
    const int*   correct = (const int*)d_in[3];
    float* out = (float*)d_out;

    fused_kernel<<<NCTA, NTHR>>>(logit_c, logit_t, q_idx, correct, out);
}

// round 8
// speedup vs baseline: 1.0435x; 1.0435x over previous
#include <cuda_runtime.h>
#include <math.h>

// Problem constants (fixed by the reference)
#define BB 256
#define TT 200
#define QQ 1000
#define TM1 199    // T - 1
#define NTHR 32    // ONE warp per student
#define KPT 7      // steps per thread (stride 32): 32*7 = 224 >= 199

// Fixed-point: per-student loss (< 8.0) scaled by 2^40; 256 of them < 2^51.
// Completion count lives at bit 54: one atomicAdd carries payload + ticket.
#define FXSCALE 1099511627776.0          // 2^40
#define CNT_ONE (1ull << 54)
#define SUM_MASK ((1ull << 54) - 1ull)

__device__ unsigned long long g_acc = 0ull;   // packed {count[63:54], fxsum[53:0]}

__global__ void __launch_bounds__(NTHR)
fused_kernel(const float* __restrict__ logit_c,
             const float* __restrict__ logit_t,
             const int*   __restrict__ q_idx,
             const int*   __restrict__ correct,
             float*       __restrict__ out)
{
    __shared__ float sh_e[TM1 + 1];    // fallback only
    __shared__ float sh_pc[TM1 + 1];   // fallback only

    const int s = blockIdx.x;          // student id
    const int i = threadIdx.x;         // lane

    float* __restrict__ p_mean = out + 1;
    float* __restrict__ gt     = out + 1 + (size_t)BB * TM1;

    // ---- Pass 1: batched index/label loads (coalesced, stride 32) ----
    int   qv[KPT];
    float av[KPT];
    bool  actv[KPT];
    #pragma unroll
    for (int k = 0; k < KPT; k++) {
        const int idx = i + k * NTHR;
        actv[k] = (idx < TM1);
        const int base = s * TT + idx + 1;
        qv[k] = actv[k] ? q_idx[base]          : 0;
        av[k] = actv[k] ? (float)correct[base] : 0.0f;
    }

    // ---- Pass 2: batched logit gathers (14 independent LDGs in flight) ----
    float xcv[KPT], xtv[KPT];
    #pragma unroll
    for (int k = 0; k < KPT; k++) {
        if (actv[k]) {
            const int idx = i + k * NTHR;
            const size_t row = (size_t)(s * TT + idx) * QQ + qv[k];
            xcv[k] = logit_c[row];
            xtv[k] = logit_t[row];
        } else { xcv[k] = 0.0f; xtv[k] = 0.0f; }
    }

    // ---- Pass 3: compute + elementwise outputs ----
    float ev[KPT], pcv[KPT];
    float e_acc = 0.0f;
    bool  allpos = true;
    #pragma unroll
    for (int k = 0; k < KPT; k++) {
        if (actv[k]) {
            const float ec = __expf(-xcv[k]);
            const float et = __expf(-xtv[k]);
            const float pc = __fdividef(1.0f, 1.0f + ec);
            const float pt = __fdividef(1.0f, 1.0f + et);
            const int idx = i + k * NTHR;
            const size_t o = (size_t)s * TM1 + idx;
            p_mean[o] = 0.5f * (pt + pc);
            gt[o]     = av[k];
            // BCE(sigmoid(x),a) = (1-a)*x + log1p(e^{-x}); both terms in one log
            const float e = (1.0f - av[k]) * (xcv[k] + xtv[k])
                          + __logf((1.0f + ec) * (1.0f + et));
            ev[k] = e; pcv[k] = pc;
            e_acc += e;
            allpos = allpos && (pc > 0.0f);
        } else { ev[k] = 0.0f; pcv[k] = 1.0f; }
    }

    // ---- Warp-only reduction: no shared mem, no __syncthreads ----
    float v = e_acc;
    #pragma unroll
    for (int off = 16; off > 0; off >>= 1)
        v += __shfl_xor_sync(0xFFFFFFFFu, v, off);
    const int wall = __all_sync(0xFFFFFFFFu, allpos);

    if (wall) {
        // Fast path: full mask, count = 199
        if (i == 0) {
            const double loss = (double)v * (1.0 / (double)TM1);
            const unsigned long long fx =
                __double2ull_rn(loss * FXSCALE) + CNT_ONE;
            const unsigned long long now = atomicAdd(&g_acc, fx) + fx;
            if ((now >> 54) == (unsigned long long)BB) {
                out[0] = (float)((double)(now & SUM_MASK) * (1.0 / FXSCALE));
                g_acc  = 0ull;              // reset for next graph replay
            }
        }
    } else {
        // Rare exact dynamic-trim fallback (warp-scope sync only)
        #pragma unroll
        for (int k = 0; k < KPT; k++) {
            const int idx = i + k * NTHR;
            if (actv[k]) { sh_e[idx] = ev[k]; sh_pc[idx] = pcv[k]; }
        }
        __syncwarp();
        if (i == 0) {
            int last = -1;
            for (int j = 0; j < TM1; j++)
                if (sh_pc[j] > 0.0f) last = j;
            if (last < 0) last = TM1 - 1;   // argmax-of-all-false convention
            float sum = 0.0f;
            for (int j = 0; j <= last; j++) sum += sh_e[j];
            const double loss = (double)sum / (double)(last + 1);
            const unsigned long long fx =
                __double2ull_rn(loss * FXSCALE) + CNT_ONE;
            const unsigned long long now = atomicAdd(&g_acc, fx) + fx;
            if ((now >> 54) == (unsigned long long)BB) {
                out[0] = (float)((double)(now & SUM_MASK) * (1.0 / FXSCALE));
                g_acc  = 0ull;
            }
        }
    }
}

extern "C" void kernel_launch(void* const* d_in, const int* in_sizes, int n_in,
                              void* d_out, int out_size)
{
    const float* logit_c = (const float*)d_in[0];
    const float* logit_t = (const float*)d_in[1];
    const int*   q_idx   = (const int*)d_in[2];
    const int*   correct = (const int*)d_in[3];
    float* out = (float*)d_out;

    fused_kernel<<<BB, NTHR>>>(logit_c, logit_t, q_idx, correct, out);
}